// round 15
// baseline (speedup 1.0000x reference)
#include <cuda_runtime.h>
#include <cuda_fp16.h>
#include <cstdint>

// ---------------------------------------------------------------------------
// R15: edge kernel processes a q-PAIR per CTA (512 thr, 16 warps): W_ss frags
// loaded once per warp feed MMAs for both q's (register B-reuse); K rows shared
// by both q's. Projections use fp16 3-pass (hi/lo images) to restore precision.
// ---------------------------------------------------------------------------

__device__ __forceinline__ void mma16816h(float c[4], const uint32_t a[4],
                                          uint32_t b0, uint32_t b1) {
    asm volatile("mma.sync.aligned.m16n8k16.row.col.f32.f16.f16.f32 "
        "{%0,%1,%2,%3},{%4,%5,%6,%7},{%8,%9},{%0,%1,%2,%3};"
        : "+f"(c[0]), "+f"(c[1]), "+f"(c[2]), "+f"(c[3])
        : "r"(a[0]), "r"(a[1]), "r"(a[2]), "r"(a[3]), "r"(b0), "r"(b1));
}
__device__ __forceinline__ uint32_t pack2h(float v0, float v1) {
    __half2 hh = __floats2half2_rn(v0, v1);
    return *(uint32_t*)&hh;
}
__device__ __forceinline__ void split2h(float v0, float v1, uint32_t& h, uint32_t& l) {
    __half2 hh = __floats2half2_rn(v0, v1);
    float h0 = __low2float(hh), h1 = __high2float(hh);
    __half2 ll = __floats2half2_rn(v0 - h0, v1 - h1);
    h = *(uint32_t*)&hh; l = *(uint32_t*)&ll;
}

// ===== scratch =====
__device__ float g_QKV[512 * 768];
__device__ float g_att[2 * 8 * 256 * 256];  // [b][h][k][q]
__device__ float g_wt[512 * 256];
__device__ uint4 g_Wss[4096];     // [ks4][tp32][lane32] fp16
__device__ uint4 g_Wed[2048];     // [ks16][tp4][lane32] fp16
__device__ uint4 g_WqkvH[24576];  // [ks16][tp48][lane32] hi
__device__ uint4 g_WqkvL[24576];  // lo
__device__ uint4 g_WndH[8192];    // [ks16][tp16][lane32]
__device__ uint4 g_WndL[8192];

__global__ void __launch_bounds__(256) zero_wt_kernel()
{
    int i = blockIdx.x * 256 + threadIdx.x;
    ((float4*)g_wt)[i] = make_float4(0.f, 0.f, 0.f, 0.f);
}

// generic hi/lo frag-image fill: W[K=256][N] -> imgH/imgL[(ks*NTP+tp)*32+lane]
__device__ __forceinline__ void fill_img2(const float* __restrict__ W,
                                          uint4* imgH, uint4* imgL,
                                          int idx, int N, int NTP) {
    int lane = idx & 31, tp = (idx >> 5) % NTP, ks = idx / (NTP * 32);
    int gq = lane >> 2, tq = lane & 3;
    uint32_t rh[4], rl[4];
#pragma unroll
    for (int r = 0; r < 4; r++) {
        int tile = 2 * tp + (r >> 1);
        int bsel = r & 1;
        int n = tile * 8 + gq;
        int e0 = ks * 16 + 2 * tq + 8 * bsel;
        split2h(W[e0 * N + n], W[(e0 + 1) * N + n], rh[r], rl[r]);
    }
    imgH[idx] = make_uint4(rh[0], rh[1], rh[2], rh[3]);
    imgL[idx] = make_uint4(rl[0], rl[1], rl[2], rl[3]);
}

// ===== prep: W_ss (16 blocks) + W_edges (8 blocks), 1-pass images =====
__global__ void __launch_bounds__(256) prep_small_kernel(
    const float* __restrict__ W_ss, const float* __restrict__ W_edges)
{
    int bidx = blockIdx.x;
    if (bidx < 16) {
        int idx = bidx * 256 + threadIdx.x;
        int lane = idx & 31, tp = (idx >> 5) & 31, ks = idx >> 10;
        int gq = lane >> 2, tq = lane & 3;
        uint32_t r4[4];
#pragma unroll
        for (int r = 0; r < 4; r++) {
            int tile = 2 * tp + (r >> 1);
            int bsel = r & 1;
            int n = tile * 8 + gq;
            int e0 = ks * 16 + 2 * tq + 8 * bsel;
            r4[r] = pack2h(W_ss[e0 * 512 + n], W_ss[(e0 + 1) * 512 + n]);
        }
        g_Wss[idx] = make_uint4(r4[0], r4[1], r4[2], r4[3]);
    } else {
        int idx = (bidx - 16) * 256 + threadIdx.x;
        int lane = idx & 31, tp = (idx >> 5) & 3, ks = idx >> 7;
        int gq = lane >> 2, tq = lane & 3;
        uint32_t r4[4];
#pragma unroll
        for (int r = 0; r < 4; r++) {
            int tile = 2 * tp + (r >> 1);
            int bsel = r & 1;
            int e = tile * 8 + gq;
            int c0 = ks * 16 + 2 * tq + 8 * bsel;
            r4[r] = pack2h(W_edges[c0 * 64 + e], W_edges[(c0 + 1) * 64 + e]);
        }
        g_Wed[idx] = make_uint4(r4[0], r4[1], r4[2], r4[3]);
    }
}
// ===== prep: W_qkv (96 blocks) + W_nodes (32 blocks), hi/lo images =====
__global__ void __launch_bounds__(256) prep_big_kernel(
    const float* __restrict__ W_qkv, const float* __restrict__ W_nodes)
{
    int bidx = blockIdx.x;
    if (bidx < 96) fill_img2(W_qkv, g_WqkvH, g_WqkvL, bidx * 256 + threadIdx.x, 768, 48);
    else           fill_img2(W_nodes, g_WndH, g_WndL, (bidx - 96) * 256 + threadIdx.x, 256, 16);
}

// ===== mma GEMM with bias, fp16 3-pass: C[M,N] = A[M,256] @ W + bias =====
__global__ void __launch_bounds__(256) gemm_mma_kernel(
    const float* __restrict__ A, const uint4* __restrict__ imgH,
    const uint4* __restrict__ imgL,
    const float* __restrict__ bias, float* __restrict__ C, int N)
{
    __shared__ uint32_t sAh[32 * 132];
    __shared__ uint32_t sAl[32 * 132];
    __shared__ float sBias[64];
    const int K = 256;
    const int nb = N >> 6;
    const int m0 = (blockIdx.x / nb) << 5, n0 = (blockIdx.x % nb) << 6;
    const int tid = threadIdx.x;
    const int warp = tid >> 5, lane = tid & 31;
    const int wm = warp >> 2, wn = warp & 3;
    const int g = lane >> 2, t = lane & 3;
    const int NTP = N >> 4;

#pragma unroll
    for (int i = 0; i < 8; i++) {
        int idx4 = tid + i * 256;
        int row = idx4 >> 6, c4 = idx4 & 63;
        float4 v = *(const float4*)&A[(m0 + row) * K + c4 * 4];
        uint32_t h0, l0, h1, l1;
        split2h(v.x, v.y, h0, l0);
        split2h(v.z, v.w, h1, l1);
        *(uint2*)&sAh[row * 132 + c4 * 2] = make_uint2(h0, h1);
        *(uint2*)&sAl[row * 132 + c4 * 2] = make_uint2(l0, l1);
    }
    if (tid < 64) sBias[tid] = bias[n0 + tid];
    __syncthreads();

    const int r0 = wm * 16 + g, r1 = r0 + 8;
    float acc0[4] = {}, acc1[4] = {};
#pragma unroll
    for (int ks = 0; ks < 16; ks++) {
        uint32_t ah[4], al[4];
        ah[0] = sAh[r0 * 132 + ks * 8 + t];     al[0] = sAl[r0 * 132 + ks * 8 + t];
        ah[1] = sAh[r1 * 132 + ks * 8 + t];     al[1] = sAl[r1 * 132 + ks * 8 + t];
        ah[2] = sAh[r0 * 132 + ks * 8 + 4 + t]; al[2] = sAl[r0 * 132 + ks * 8 + 4 + t];
        ah[3] = sAh[r1 * 132 + ks * 8 + 4 + t]; al[3] = sAl[r1 * 132 + ks * 8 + 4 + t];
        int bi = ((ks * NTP) + (n0 >> 4) + wn) * 32 + lane;
        uint4 bh = imgH[bi];
        uint4 bl = imgL[bi];
        mma16816h(acc0, ah, bh.x, bh.y); mma16816h(acc1, ah, bh.z, bh.w);
        mma16816h(acc0, al, bh.x, bh.y); mma16816h(acc1, al, bh.z, bh.w);
        mma16816h(acc0, ah, bl.x, bl.y); mma16816h(acc1, ah, bl.z, bl.w);
    }
    const int cl = wn * 16 + 2 * t;
    const int c0 = n0 + cl;
    *(float2*)&C[(m0 + r0) * N + c0]     = make_float2(acc0[0] + sBias[cl],   acc0[1] + sBias[cl+1]);
    *(float2*)&C[(m0 + r1) * N + c0]     = make_float2(acc0[2] + sBias[cl],   acc0[3] + sBias[cl+1]);
    *(float2*)&C[(m0 + r0) * N + c0 + 8] = make_float2(acc1[0] + sBias[cl+8], acc1[1] + sBias[cl+9]);
    *(float2*)&C[(m0 + r1) * N + c0 + 8] = make_float2(acc1[2] + sBias[cl+8], acc1[3] + sBias[cl+9]);
}

// ===== edge kernel: 512 threads, q-PAIR per CTA, 4 kt =====
// GEMM1 warps: wm=(warp>>3)&1 (k-row half), wn=warp&7 (32-col slice = head wn).
// Each B frag loaded once, MMA'd for both q's. K loads shared by both q's.
__global__ void __launch_bounds__(512, 1) edge_mma_kernel(
    const float* __restrict__ edges, const float* __restrict__ b_ss,
    const float* __restrict__ b_edges, float* __restrict__ out_edges)
{
    extern __shared__ float sm[];
    float* sE   = sm;                          // [2q][4kt][32][68] = 17408 f
    float* sQ   = sm + 17408;                  // [2][256]
    float* sBsh = sm + 17920;                  // 256
    float* sBsc = sm + 18176;                  // 256
    float* sBed = sm + 18432;                  // 64
    uint32_t* sA2 = (uint32_t*)(sm + 18496);   // [2q][32][132]

    const int tid = threadIdx.x;
    const int warp = tid >> 5, lane = tid & 31;
    const int wm = (warp >> 3) & 1, wn = warp & 7;
    const int g = lane >> 2, t = lane & 3;
    const int b = blockIdx.x >> 8;
    const int q0g = ((blockIdx.x >> 1) & 127) * 2;
    const int half = blockIdx.x & 1;
    const int r0 = wm * 16 + g, r1 = r0 + 8;

    // stage: both q's edge tiles (4096 float4), q rows, biases
#pragma unroll
    for (int i = 0; i < 8; i++) {
        int idx4 = tid + i * 512;
        int qs = idx4 >> 11;
        int rest = idx4 & 2047;
        int tile = rest >> 9, row = (rest >> 4) & 31, ec = (rest & 15) << 2;
        const float* ep = edges + (((size_t)(b*256 + q0g + qs)) * 256 + half*128) * 64;
        float4 v = *(const float4*)(ep + (size_t)(tile*32 + row) * 64 + ec);
        *(float4*)&sE[qs*8704 + tile*2176 + row*68 + ec] = v;
    }
    if (tid < 128) {
        int qs = tid >> 6, off = (tid & 63) << 2;
        *(float4*)&sQ[qs*256 + off] = *(const float4*)&g_QKV[(b*256 + q0g + qs)*768 + off];
    } else if (tid < 192) *(float4*)&sBsh[(tid-128)*4] = *(const float4*)&b_ss[(tid-128)*4];
    else if (tid < 256)   *(float4*)&sBsc[(tid-192)*4] = *(const float4*)&b_ss[256+(tid-192)*4];
    else if (tid < 272)   *(float4*)&sBed[(tid-256)*4] = *(const float4*)&b_edges[(tid-256)*4];
    __syncthreads();

    for (int kt4 = 0; kt4 < 4; kt4++) {
        const int kt = half * 4 + kt4;
        const float* sE0 = sE + kt4 * 2176;            // q0 tile
        const float* sE1 = sE + 8704 + kt4 * 2176;     // q1 tile

        // ---- GEMM1: acc[q][0..3]=shift lt, [4..7]=scale lt ----
        float acc[2][8][4];
#pragma unroll
        for (int qq = 0; qq < 2; qq++)
#pragma unroll
            for (int i = 0; i < 8; i++)
                { acc[qq][i][0]=acc[qq][i][1]=acc[qq][i][2]=acc[qq][i][3]=0.f; }
#pragma unroll
        for (int ks = 0; ks < 4; ks++) {
            uint32_t A0[4], A1[4];
            {
                int e0 = ks * 16 + 2 * t;
                float2 v00 = *(const float2*)&sE0[r0*68 + e0];
                float2 v10 = *(const float2*)&sE0[r1*68 + e0];
                float2 v01 = *(const float2*)&sE0[r0*68 + e0 + 8];
                float2 v11 = *(const float2*)&sE0[r1*68 + e0 + 8];
                A0[0] = pack2h(v00.x, v00.y); A0[1] = pack2h(v10.x, v10.y);
                A0[2] = pack2h(v01.x, v01.y); A0[3] = pack2h(v11.x, v11.y);
                float2 w00 = *(const float2*)&sE1[r0*68 + e0];
                float2 w10 = *(const float2*)&sE1[r1*68 + e0];
                float2 w01 = *(const float2*)&sE1[r0*68 + e0 + 8];
                float2 w11 = *(const float2*)&sE1[r1*68 + e0 + 8];
                A1[0] = pack2h(w00.x, w00.y); A1[1] = pack2h(w10.x, w10.y);
                A1[2] = pack2h(w01.x, w01.y); A1[3] = pack2h(w11.x, w11.y);
            }
            uint4 bsh0 = g_Wss[(ks*32 + 2*wn + 0)*32 + lane];
            uint4 bsh1 = g_Wss[(ks*32 + 2*wn + 1)*32 + lane];
            uint4 bsc0 = g_Wss[(ks*32 + 16 + 2*wn + 0)*32 + lane];
            uint4 bsc1 = g_Wss[(ks*32 + 16 + 2*wn + 1)*32 + lane];
            mma16816h(acc[0][0], A0, bsh0.x, bsh0.y); mma16816h(acc[0][1], A0, bsh0.z, bsh0.w);
            mma16816h(acc[0][2], A0, bsh1.x, bsh1.y); mma16816h(acc[0][3], A0, bsh1.z, bsh1.w);
            mma16816h(acc[0][4], A0, bsc0.x, bsc0.y); mma16816h(acc[0][5], A0, bsc0.z, bsc0.w);
            mma16816h(acc[0][6], A0, bsc1.x, bsc1.y); mma16816h(acc[0][7], A0, bsc1.z, bsc1.w);
            mma16816h(acc[1][0], A1, bsh0.x, bsh0.y); mma16816h(acc[1][1], A1, bsh0.z, bsh0.w);
            mma16816h(acc[1][2], A1, bsh1.x, bsh1.y); mma16816h(acc[1][3], A1, bsh1.z, bsh1.w);
            mma16816h(acc[1][4], A1, bsc0.x, bsc0.y); mma16816h(acc[1][5], A1, bsc0.z, bsc0.w);
            mma16816h(acc[1][6], A1, bsc1.x, bsc1.y); mma16816h(acc[1][7], A1, bsc1.z, bsc1.w);
        }

        // ---- epilogue: K shared by both q's; warp = head wn ----
        const float* kr0 = &g_QKV[(b*256 + kt*32 + r0)*768 + 256 + wn*32];
        const float* kr1 = &g_QKV[(b*256 + kt*32 + r1)*768 + 256 + wn*32];
        float lg[2][2] = {};
#pragma unroll
        for (int lt = 0; lt < 4; lt++) {
            int cc = lt * 8 + 2 * t;           // col within warp's 32-col window
            int c0g = wn * 32 + cc;            // col in 256-space
            float2 k0 = *(const float2*)(kr0 + cc);
            float2 k1 = *(const float2*)(kr1 + cc);
            float2 sc = *(const float2*)&sBsc[c0g];
            float2 sh = *(const float2*)&sBsh[c0g];
            int cp = wn * 16 + lt * 4 + t;
#pragma unroll
            for (int qq = 0; qq < 2; qq++) {
                float qa = sQ[qq*256 + c0g], qb = sQ[qq*256 + c0g + 1];
                float qk00 = qa * k0.x, qk01 = qb * k0.y;
                float qk10 = qa * k1.x, qk11 = qb * k1.y;
                float ne00 = fmaf(qk00, acc[qq][4+lt][0] + sc.x, qk00) + acc[qq][lt][0] + sh.x;
                float ne01 = fmaf(qk01, acc[qq][4+lt][1] + sc.y, qk01) + acc[qq][lt][1] + sh.y;
                float ne10 = fmaf(qk10, acc[qq][4+lt][2] + sc.x, qk10) + acc[qq][lt][2] + sh.x;
                float ne11 = fmaf(qk11, acc[qq][4+lt][3] + sc.y, qk11) + acc[qq][lt][3] + sh.y;
                lg[qq][0] += ne00 + ne01;
                lg[qq][1] += ne10 + ne11;
                float p00 = ne00 > 0.f ? ne00 : 0.1f*ne00;
                float p01 = ne01 > 0.f ? ne01 : 0.1f*ne01;
                float p10 = ne10 > 0.f ? ne10 : 0.1f*ne10;
                float p11 = ne11 > 0.f ? ne11 : 0.1f*ne11;
                sA2[qq*4224 + r0*132 + cp] = pack2h(p00, p01);
                sA2[qq*4224 + r1*132 + cp] = pack2h(p10, p11);
            }
        }
#pragma unroll
        for (int qq = 0; qq < 2; qq++) {
            lg[qq][0] += __shfl_xor_sync(0xffffffffu, lg[qq][0], 1);
            lg[qq][0] += __shfl_xor_sync(0xffffffffu, lg[qq][0], 2);
            lg[qq][1] += __shfl_xor_sync(0xffffffffu, lg[qq][1], 1);
            lg[qq][1] += __shfl_xor_sync(0xffffffffu, lg[qq][1], 2);
        }
        if (t == 0) {
            const float SC = 0.17677669529663687f;
            size_t base = ((size_t)(b*8 + wn)) * 256 + kt*32;
            g_att[(base + r0)*256 + q0g + 0] = lg[0][0] * SC;
            g_att[(base + r0)*256 + q0g + 1] = lg[1][0] * SC;
            g_att[(base + r1)*256 + q0g + 0] = lg[0][1] * SC;
            g_att[(base + r1)*256 + q0g + 1] = lg[1][1] * SC;
        }
        __syncthreads();

        // ---- GEMM2 per q: warps 0-7 -> q0, 8-15 -> q1 ----
        {
            const int qg = warp >> 3;
            const int w8 = warp & 7;
            const int wm2 = w8 >> 2, wn2 = w8 & 3;
            const int s0 = wm2 * 16 + g, s1 = s0 + 8;
            const uint32_t* a2 = sA2 + qg * 4224;
            float c2a[4] = {}, c2b[4] = {};
#pragma unroll
            for (int ks = 0; ks < 16; ks++) {
                uint32_t ah[4];
                ah[0] = a2[s0*132 + ks*8 + t];
                ah[1] = a2[s1*132 + ks*8 + t];
                ah[2] = a2[s0*132 + ks*8 + 4 + t];
                ah[3] = a2[s1*132 + ks*8 + 4 + t];
                uint4 bh = g_Wed[(ks*4 + wn2)*32 + lane];
                mma16816h(c2a, ah, bh.x, bh.y); mma16816h(c2b, ah, bh.z, bh.w);
            }
            float* op = out_edges + (((size_t)(b*256 + q0g + qg))*256 + kt*32)*64;
            int e0 = wn2 * 16 + 2 * t;
            *(float2*)&op[s0*64 + e0]     = make_float2(c2a[0] + sBed[e0],   c2a[1] + sBed[e0+1]);
            *(float2*)&op[s1*64 + e0]     = make_float2(c2a[2] + sBed[e0],   c2a[3] + sBed[e0+1]);
            *(float2*)&op[s0*64 + e0 + 8] = make_float2(c2b[0] + sBed[e0+8], c2b[1] + sBed[e0+9]);
            *(float2*)&op[s1*64 + e0 + 8] = make_float2(c2b[2] + sBed[e0+8], c2b[3] + sBed[e0+9]);
        }
        __syncthreads();
    }
}

// ===== softmax over q for each (b,h,k) =====
__global__ void __launch_bounds__(256) softmax_q_kernel(float* __restrict__ lg)
{
    const int row = blockIdx.x * 8 + (threadIdx.x >> 5);
    const int lane = threadIdx.x & 31;
    float* p = lg + (size_t)row * 256;
    float4 v0 = *(float4*)&p[lane * 8];
    float4 v1 = *(float4*)&p[lane * 8 + 4];
    float v[8] = { v0.x, v0.y, v0.z, v0.w, v1.x, v1.y, v1.z, v1.w };
    float m = v[0];
#pragma unroll
    for (int i = 1; i < 8; i++) m = fmaxf(m, v[i]);
#pragma unroll
    for (int o = 16; o > 0; o >>= 1) m = fmaxf(m, __shfl_xor_sync(0xffffffffu, m, o));
    float s = 0.f;
#pragma unroll
    for (int i = 0; i < 8; i++) { v[i] = __expf(v[i] - m); s += v[i]; }
#pragma unroll
    for (int o = 16; o > 0; o >>= 1) s += __shfl_xor_sync(0xffffffffu, s, o);
    float inv = 1.f / s;
    *(float4*)&p[lane * 8]     = make_float4(v[0]*inv, v[1]*inv, v[2]*inv, v[3]*inv);
    *(float4*)&p[lane * 8 + 4] = make_float4(v[4]*inv, v[5]*inv, v[6]*inv, v[7]*inv);
}

// ===== attn @ V, k-split, atomics into zeroed g_wt =====
__global__ void __launch_bounds__(256) attnv2_kernel(const float* __restrict__ att)
{
    __shared__ float sv[32][32];
    const int b = blockIdx.z >> 3, h = blockIdx.z & 7;
    const int kc = blockIdx.y, qc = blockIdx.x;
    const int dg = threadIdx.x >> 6, qq = threadIdx.x & 63;
    const int q = qc * 64 + qq;
    {
        int row = threadIdx.x >> 3, c4 = (threadIdx.x & 7) << 2;
        *(float4*)&sv[row][c4] =
            *(const float4*)&g_QKV[((b << 8) + kc * 32 + row) * 768 + 512 + h * 32 + c4];
    }
    __syncthreads();
    const float* ap = att + (((size_t)((b << 3) + h)) * 256 + kc * 32) * 256 + q;
    float acc[8] = {};
#pragma unroll
    for (int kk = 0; kk < 32; kk++) {
        float a = ap[(size_t)kk * 256];
        float4 u0 = *(float4*)&sv[kk][dg * 8];
        float4 u1 = *(float4*)&sv[kk][dg * 8 + 4];
        acc[0]+=a*u0.x; acc[1]+=a*u0.y; acc[2]+=a*u0.z; acc[3]+=a*u0.w;
        acc[4]+=a*u1.x; acc[5]+=a*u1.y; acc[6]+=a*u1.z; acc[7]+=a*u1.w;
    }
    float* wp = &g_wt[((b << 8) + q) * 256 + h * 32 + dg * 8];
#pragma unroll
    for (int j = 0; j < 8; j++) atomicAdd(wp + j, acc[j]);
}

// ===== launch =====
extern "C" void kernel_launch(void* const* d_in, const int* in_sizes, int n_in,
                              void* d_out, int out_size)
{
    const float* nodes   = (const float*)d_in[0];
    const float* edges   = (const float*)d_in[1];
    const float* W_qkv   = (const float*)d_in[2];
    const float* b_qkv   = (const float*)d_in[3];
    const float* W_ss    = (const float*)d_in[4];
    const float* b_ss    = (const float*)d_in[5];
    const float* W_nodes = (const float*)d_in[6];
    const float* b_nodes = (const float*)d_in[7];
    const float* W_edges = (const float*)d_in[8];
    const float* b_edges = (const float*)d_in[9];

    float* out_nodes = (float*)d_out;
    float* out_edges = out_nodes + 512 * 256;

    float *qkvp = nullptr, *attp = nullptr, *wtp = nullptr;
    cudaGetSymbolAddress((void**)&qkvp, g_QKV);
    cudaGetSymbolAddress((void**)&attp, g_att);
    cudaGetSymbolAddress((void**)&wtp, g_wt);
    uint4 *wqh = nullptr, *wql = nullptr, *wnh = nullptr, *wnl = nullptr;
    cudaGetSymbolAddress((void**)&wqh, g_WqkvH);
    cudaGetSymbolAddress((void**)&wql, g_WqkvL);
    cudaGetSymbolAddress((void**)&wnh, g_WndH);
    cudaGetSymbolAddress((void**)&wnl, g_WndL);

    // sE 17408 + sQ 512 + biases 576 + sA2 8448 = 26944 floats = 107776 B
    const int EDGE_SMEM = 26944 * sizeof(float);
    cudaFuncSetAttribute(edge_mma_kernel,
                         cudaFuncAttributeMaxDynamicSharedMemorySize, EDGE_SMEM);

    // edge_mma stays the 4th launch (ncu capture point)
    prep_big_kernel<<<128, 256>>>(W_qkv, W_nodes);
    prep_small_kernel<<<24, 256>>>(W_ss, W_edges);
    gemm_mma_kernel<<<(512/32)*(768/64), 256>>>(nodes, wqh, wql, b_qkv, qkvp, 768);
    edge_mma_kernel<<<512, 512, EDGE_SMEM>>>(edges, b_ss, b_edges, out_edges);
    zero_wt_kernel<<<128, 256>>>();
    softmax_q_kernel<<<512, 256>>>(attp);
    attnv2_kernel<<<dim3(4, 8, 16), 256>>>(attp);
    gemm_mma_kernel<<<(512/32)*(256/64), 256>>>(wtp, wnh, wnl, b_nodes, out_nodes, 256);
}

// round 16
// speedup vs baseline: 1.1325x; 1.1325x over previous
#include <cuda_runtime.h>
#include <cuda_fp16.h>
#include <cstdint>

// ---------------------------------------------------------------------------
// R16: edge = R12 structure (256thr, occ2, grid 1024, 4kt) with K read from a
// fragment-ordered fp16 image g_Kf (4 coalesced LDG.128/thread/kt instead of
// 16 scattered LDG.64). Projections fp16 3-pass (hi/lo images).
// ---------------------------------------------------------------------------

__device__ __forceinline__ void mma16816h(float c[4], const uint32_t a[4],
                                          uint32_t b0, uint32_t b1) {
    asm volatile("mma.sync.aligned.m16n8k16.row.col.f32.f16.f16.f32 "
        "{%0,%1,%2,%3},{%4,%5,%6,%7},{%8,%9},{%0,%1,%2,%3};"
        : "+f"(c[0]), "+f"(c[1]), "+f"(c[2]), "+f"(c[3])
        : "r"(a[0]), "r"(a[1]), "r"(a[2]), "r"(a[3]), "r"(b0), "r"(b1));
}
__device__ __forceinline__ uint32_t pack2h(float v0, float v1) {
    __half2 hh = __floats2half2_rn(v0, v1);
    return *(uint32_t*)&hh;
}
__device__ __forceinline__ void split2h(float v0, float v1, uint32_t& h, uint32_t& l) {
    __half2 hh = __floats2half2_rn(v0, v1);
    float h0 = __low2float(hh), h1 = __high2float(hh);
    __half2 ll = __floats2half2_rn(v0 - h0, v1 - h1);
    h = *(uint32_t*)&hh; l = *(uint32_t*)&ll;
}

// ===== scratch =====
__device__ float g_QKV[512 * 768];
__device__ float g_att[2 * 8 * 256 * 256];  // [b][h][k][q]
__device__ float g_wt[512 * 256];
__device__ uint4 g_Wss[4096];     // [ks4][tp32][lane32] fp16
__device__ uint4 g_Wed[2048];     // [ks16][tp4][lane32] fp16
__device__ uint4 g_WqkvH[24576];  // hi
__device__ uint4 g_WqkvL[24576];  // lo
__device__ uint4 g_WndH[8192];
__device__ uint4 g_WndL[8192];
__device__ uint4 g_Kf[16384];     // frag-ordered K fp16: [b][kt][warp][lane][4]

__global__ void __launch_bounds__(256) zero_wt_kernel()
{
    int i = blockIdx.x * 256 + threadIdx.x;
    ((float4*)g_wt)[i] = make_float4(0.f, 0.f, 0.f, 0.f);
}

__device__ __forceinline__ void fill_img2(const float* __restrict__ W,
                                          uint4* imgH, uint4* imgL,
                                          int idx, int N, int NTP) {
    int lane = idx & 31, tp = (idx >> 5) % NTP, ks = idx / (NTP * 32);
    int gq = lane >> 2, tq = lane & 3;
    uint32_t rh[4], rl[4];
#pragma unroll
    for (int r = 0; r < 4; r++) {
        int tile = 2 * tp + (r >> 1);
        int bsel = r & 1;
        int n = tile * 8 + gq;
        int e0 = ks * 16 + 2 * tq + 8 * bsel;
        split2h(W[e0 * N + n], W[(e0 + 1) * N + n], rh[r], rl[r]);
    }
    imgH[idx] = make_uint4(rh[0], rh[1], rh[2], rh[3]);
    imgL[idx] = make_uint4(rl[0], rl[1], rl[2], rl[3]);
}

// ===== merged prep: 152 blocks =====
// [0,96) Wqkv hi/lo, [96,128) Wnodes hi/lo, [128,144) Wss, [144,152) Wedges
__global__ void __launch_bounds__(256) prep_all_kernel(
    const float* __restrict__ W_qkv, const float* __restrict__ W_nodes,
    const float* __restrict__ W_ss, const float* __restrict__ W_edges)
{
    int bidx = blockIdx.x;
    if (bidx < 96) {
        fill_img2(W_qkv, g_WqkvH, g_WqkvL, bidx * 256 + threadIdx.x, 768, 48);
    } else if (bidx < 128) {
        fill_img2(W_nodes, g_WndH, g_WndL, (bidx - 96) * 256 + threadIdx.x, 256, 16);
    } else if (bidx < 144) {
        int idx = (bidx - 128) * 256 + threadIdx.x;
        int lane = idx & 31, tp = (idx >> 5) & 31, ks = idx >> 10;
        int gq = lane >> 2, tq = lane & 3;
        uint32_t r4[4];
#pragma unroll
        for (int r = 0; r < 4; r++) {
            int tile = 2 * tp + (r >> 1);
            int bsel = r & 1;
            int n = tile * 8 + gq;
            int e0 = ks * 16 + 2 * tq + 8 * bsel;
            r4[r] = pack2h(W_ss[e0 * 512 + n], W_ss[(e0 + 1) * 512 + n]);
        }
        g_Wss[idx] = make_uint4(r4[0], r4[1], r4[2], r4[3]);
    } else {
        int idx = (bidx - 144) * 256 + threadIdx.x;
        int lane = idx & 31, tp = (idx >> 5) & 3, ks = idx >> 7;
        int gq = lane >> 2, tq = lane & 3;
        uint32_t r4[4];
#pragma unroll
        for (int r = 0; r < 4; r++) {
            int tile = 2 * tp + (r >> 1);
            int bsel = r & 1;
            int e = tile * 8 + gq;
            int c0 = ks * 16 + 2 * tq + 8 * bsel;
            r4[r] = pack2h(W_edges[c0 * 64 + e], W_edges[(c0 + 1) * 64 + e]);
        }
        g_Wed[idx] = make_uint4(r4[0], r4[1], r4[2], r4[3]);
    }
}

// ===== kfrag: K (qkv cols 256..511) -> frag-ordered fp16 image =====
// idx(uint4) bits: j(2) | lane(5) | warp(3) | kt(3) | b(1)
__global__ void __launch_bounds__(256) kfrag_kernel()
{
    int idx = blockIdx.x * 256 + threadIdx.x;     // 0..16383
    int j = idx & 3, lane = (idx >> 2) & 31, w = (idx >> 7) & 7;
    int kt = (idx >> 10) & 7, b = idx >> 13;
    int wm = w >> 2, wn = w & 3;
    int g = lane >> 2, t = lane & 3;
    int r = wm * 16 + g + ((j >> 1) ? 8 : 0);
    int ltb = (j & 1) * 4;
    const float* p = g_QKV + (size_t)(b*256 + kt*32 + r) * 768 + 256 + wn*64 + 2*t;
    uint32_t o[4];
#pragma unroll
    for (int i = 0; i < 4; i++) {
        float2 v = *(const float2*)(p + (ltb + i) * 8);
        o[i] = pack2h(v.x, v.y);
    }
    g_Kf[idx] = make_uint4(o[0], o[1], o[2], o[3]);
}

// ===== mma GEMM with bias, fp16 3-pass =====
__global__ void __launch_bounds__(256) gemm_mma_kernel(
    const float* __restrict__ A, const uint4* __restrict__ imgH,
    const uint4* __restrict__ imgL,
    const float* __restrict__ bias, float* __restrict__ C, int N)
{
    __shared__ uint32_t sAh[32 * 132];
    __shared__ uint32_t sAl[32 * 132];
    __shared__ float sBias[64];
    const int K = 256;
    const int nb = N >> 6;
    const int m0 = (blockIdx.x / nb) << 5, n0 = (blockIdx.x % nb) << 6;
    const int tid = threadIdx.x;
    const int warp = tid >> 5, lane = tid & 31;
    const int wm = warp >> 2, wn = warp & 3;
    const int g = lane >> 2, t = lane & 3;
    const int NTP = N >> 4;

#pragma unroll
    for (int i = 0; i < 8; i++) {
        int idx4 = tid + i * 256;
        int row = idx4 >> 6, c4 = idx4 & 63;
        float4 v = *(const float4*)&A[(m0 + row) * K + c4 * 4];
        uint32_t h0, l0, h1, l1;
        split2h(v.x, v.y, h0, l0);
        split2h(v.z, v.w, h1, l1);
        *(uint2*)&sAh[row * 132 + c4 * 2] = make_uint2(h0, h1);
        *(uint2*)&sAl[row * 132 + c4 * 2] = make_uint2(l0, l1);
    }
    if (tid < 64) sBias[tid] = bias[n0 + tid];
    __syncthreads();

    const int r0 = wm * 16 + g, r1 = r0 + 8;
    float acc0[4] = {}, acc1[4] = {};
#pragma unroll
    for (int ks = 0; ks < 16; ks++) {
        uint32_t ah[4], al[4];
        ah[0] = sAh[r0 * 132 + ks * 8 + t];     al[0] = sAl[r0 * 132 + ks * 8 + t];
        ah[1] = sAh[r1 * 132 + ks * 8 + t];     al[1] = sAl[r1 * 132 + ks * 8 + t];
        ah[2] = sAh[r0 * 132 + ks * 8 + 4 + t]; al[2] = sAl[r0 * 132 + ks * 8 + 4 + t];
        ah[3] = sAh[r1 * 132 + ks * 8 + 4 + t]; al[3] = sAl[r1 * 132 + ks * 8 + 4 + t];
        int bi = ((ks * NTP) + (n0 >> 4) + wn) * 32 + lane;
        uint4 bh = imgH[bi];
        uint4 bl = imgL[bi];
        mma16816h(acc0, ah, bh.x, bh.y); mma16816h(acc1, ah, bh.z, bh.w);
        mma16816h(acc0, al, bh.x, bh.y); mma16816h(acc1, al, bh.z, bh.w);
        mma16816h(acc0, ah, bl.x, bl.y); mma16816h(acc1, ah, bl.z, bl.w);
    }
    const int cl = wn * 16 + 2 * t;
    const int c0 = n0 + cl;
    *(float2*)&C[(m0 + r0) * N + c0]     = make_float2(acc0[0] + sBias[cl],   acc0[1] + sBias[cl+1]);
    *(float2*)&C[(m0 + r1) * N + c0]     = make_float2(acc0[2] + sBias[cl],   acc0[3] + sBias[cl+1]);
    *(float2*)&C[(m0 + r0) * N + c0 + 8] = make_float2(acc1[0] + sBias[cl+8], acc1[1] + sBias[cl+9]);
    *(float2*)&C[(m0 + r1) * N + c0 + 8] = make_float2(acc1[2] + sBias[cl+8], acc1[3] + sBias[cl+9]);
}

// ===== main edge kernel: fp16 1-pass, CTA=(b,q,half), 4 kt, K via g_Kf =====
__global__ void __launch_bounds__(256, 2) edge_mma_kernel(
    const float* __restrict__ edges, const float* __restrict__ b_ss,
    const float* __restrict__ b_edges, float* __restrict__ out_edges)
{
    extern __shared__ float sm[];
    float* sE   = sm;                    // [4][32][68]
    float* sQ   = sm + 8704;             // 256
    float* sBsh = sQ + 256;              // 256
    float* sBsc = sBsh + 256;            // 256
    float* sBed = sBsc + 256;            // 64
    uint32_t* sA2h = (uint32_t*)(sBed + 64);  // [32][132] fp16x2

    const int tid = threadIdx.x;
    const int warp = tid >> 5, lane = tid & 31;
    const int wm = warp >> 2, wn = warp & 3;
    const int g = lane >> 2, t = lane & 3;
    const int b = blockIdx.x >> 9;
    const int q = (blockIdx.x >> 1) & 255;
    const int half = blockIdx.x & 1;
    const int r0 = wm * 16 + g, r1 = r0 + 8;

    const float* ep = edges + (((size_t)(b * 256 + q)) * 256 + half * 128) * 64;

    if (tid < 64)       *(float4*)&sQ[tid*4]   = *(const float4*)&g_QKV[(b*256+q)*768 + tid*4];
    else if (tid < 128) *(float4*)&sBsh[(tid-64)*4]  = *(const float4*)&b_ss[(tid-64)*4];
    else if (tid < 192) *(float4*)&sBsc[(tid-128)*4] = *(const float4*)&b_ss[256+(tid-128)*4];
    else if (tid < 208) *(float4*)&sBed[(tid-192)*4] = *(const float4*)&b_edges[(tid-192)*4];

    {
        const int er = tid >> 4, ec = (tid & 15) << 2;
#pragma unroll
        for (int i = 0; i < 8; i++) {
            int tile = i >> 1;
            int row = er + (i & 1) * 16;
            float4 v = *(const float4*)(ep + (size_t)(tile*32 + row) * 64 + ec);
            *(float4*)&sE[tile*2176 + row*68 + ec] = v;
        }
    }
    __syncthreads();

    for (int kt4 = 0; kt4 < 4; kt4++) {
        const int kt = half * 4 + kt4;
        const float* sEc = sE + kt4 * 2176;

        // ---- GEMM1: shift(acc 0..7) + scale(acc 8..15), fp16 1-pass ----
        float acc[16][4];
#pragma unroll
        for (int i = 0; i < 16; i++) { acc[i][0]=acc[i][1]=acc[i][2]=acc[i][3]=0.f; }
#pragma unroll
        for (int ks = 0; ks < 4; ks++) {
            uint32_t Ah[4];
            {
                int e0 = ks * 16 + 2 * t;
                float2 v00 = *(const float2*)&sEc[r0*68 + e0];
                float2 v10 = *(const float2*)&sEc[r1*68 + e0];
                float2 v01 = *(const float2*)&sEc[r0*68 + e0 + 8];
                float2 v11 = *(const float2*)&sEc[r1*68 + e0 + 8];
                Ah[0] = pack2h(v00.x, v00.y);
                Ah[1] = pack2h(v10.x, v10.y);
                Ah[2] = pack2h(v01.x, v01.y);
                Ah[3] = pack2h(v11.x, v11.y);
            }
#pragma unroll
            for (int tpi = 0; tpi < 4; tpi++) {
                uint4 bh = g_Wss[(ks*32 + 4*wn + tpi)*32 + lane];
                mma16816h(acc[2*tpi],   Ah, bh.x, bh.y);
                mma16816h(acc[2*tpi+1], Ah, bh.z, bh.w);
                uint4 ch = g_Wss[(ks*32 + 16 + 4*wn + tpi)*32 + lane];
                mma16816h(acc[8+2*tpi],   Ah, ch.x, ch.y);
                mma16816h(acc[8+2*tpi+1], Ah, ch.z, ch.w);
            }
        }

        // ---- K frags: 4 coalesced LDG.128 ----
        uint32_t kr[16];
        {
            uint4* k4 = (uint4*)kr;
            size_t kb = ((((size_t)b*8 + kt)*8 + warp)*32 + lane)*4;
            k4[0] = g_Kf[kb];     k4[1] = g_Kf[kb + 1];
            k4[2] = g_Kf[kb + 2]; k4[3] = g_Kf[kb + 3];
        }

        // ---- epilogue: ne, logits, lrelu -> sA2 ----
        float lg00 = 0.f, lg01 = 0.f, lg10 = 0.f, lg11 = 0.f;
#pragma unroll
        for (int lt = 0; lt < 8; lt++) {
            int c0 = wn * 64 + lt * 8 + 2 * t;
            float2 k0v = __half22float2(*(__half2*)&kr[lt]);
            float2 k1v = __half22float2(*(__half2*)&kr[8 + lt]);
            float q0 = sQ[c0], q1 = sQ[c0+1];
            float qk00 = q0 * k0v.x, qk01 = q1 * k0v.y;
            float qk10 = q0 * k1v.x, qk11 = q1 * k1v.y;
            float ne00 = fmaf(qk00, acc[8+lt][0] + sBsc[c0],   qk00) + acc[lt][0] + sBsh[c0];
            float ne01 = fmaf(qk01, acc[8+lt][1] + sBsc[c0+1], qk01) + acc[lt][1] + sBsh[c0+1];
            float ne10 = fmaf(qk10, acc[8+lt][2] + sBsc[c0],   qk10) + acc[lt][2] + sBsh[c0];
            float ne11 = fmaf(qk11, acc[8+lt][3] + sBsc[c0+1], qk11) + acc[lt][3] + sBsh[c0+1];
            if (lt < 4) { lg00 += ne00 + ne01; lg10 += ne10 + ne11; }
            else        { lg01 += ne00 + ne01; lg11 += ne10 + ne11; }
            float p00 = ne00 > 0.f ? ne00 : 0.1f*ne00;
            float p01 = ne01 > 0.f ? ne01 : 0.1f*ne01;
            float p10 = ne10 > 0.f ? ne10 : 0.1f*ne10;
            float p11 = ne11 > 0.f ? ne11 : 0.1f*ne11;
            int cp = wn * 32 + lt * 4 + t;
            sA2h[r0*132 + cp] = pack2h(p00, p01);
            sA2h[r1*132 + cp] = pack2h(p10, p11);
        }
        lg00 += __shfl_xor_sync(0xffffffffu, lg00, 1); lg00 += __shfl_xor_sync(0xffffffffu, lg00, 2);
        lg01 += __shfl_xor_sync(0xffffffffu, lg01, 1); lg01 += __shfl_xor_sync(0xffffffffu, lg01, 2);
        lg10 += __shfl_xor_sync(0xffffffffu, lg10, 1); lg10 += __shfl_xor_sync(0xffffffffu, lg10, 2);
        lg11 += __shfl_xor_sync(0xffffffffu, lg11, 1); lg11 += __shfl_xor_sync(0xffffffffu, lg11, 2);
        if (t == 0) {
            const float SC = 0.17677669529663687f;
            int kk = kt * 32;
            g_att[(((size_t)(b*8 + 2*wn+0))*256 + kk + r0)*256 + q] = lg00 * SC;
            g_att[(((size_t)(b*8 + 2*wn+1))*256 + kk + r0)*256 + q] = lg01 * SC;
            g_att[(((size_t)(b*8 + 2*wn+0))*256 + kk + r1)*256 + q] = lg10 * SC;
            g_att[(((size_t)(b*8 + 2*wn+1))*256 + kk + r1)*256 + q] = lg11 * SC;
        }
        __syncthreads();

        // ---- GEMM2: out = lrelu(ne)[32,256] @ W_edges[256,64], fp16 1-pass ----
        float c2a[4] = {}, c2b[4] = {};
#pragma unroll
        for (int ks = 0; ks < 16; ks++) {
            uint32_t ah[4];
            ah[0] = sA2h[r0*132 + ks*8 + t];
            ah[1] = sA2h[r1*132 + ks*8 + t];
            ah[2] = sA2h[r0*132 + ks*8 + 4 + t];
            ah[3] = sA2h[r1*132 + ks*8 + 4 + t];
            uint4 bh = g_Wed[(ks*4 + wn)*32 + lane];
            mma16816h(c2a, ah, bh.x, bh.y); mma16816h(c2b, ah, bh.z, bh.w);
        }
        float* op = out_edges + (((size_t)(b*256+q))*256 + kt*32)*64;
        {
            int e0 = wn * 16 + 2 * t;
            *(float2*)&op[r0*64 + e0]     = make_float2(c2a[0] + sBed[e0],   c2a[1] + sBed[e0+1]);
            *(float2*)&op[r1*64 + e0]     = make_float2(c2a[2] + sBed[e0],   c2a[3] + sBed[e0+1]);
            *(float2*)&op[r0*64 + e0 + 8] = make_float2(c2b[0] + sBed[e0+8], c2b[1] + sBed[e0+9]);
            *(float2*)&op[r1*64 + e0 + 8] = make_float2(c2b[2] + sBed[e0+8], c2b[3] + sBed[e0+9]);
        }
        __syncthreads();
    }
}

// ===== softmax over q for each (b,h,k) =====
__global__ void __launch_bounds__(256) softmax_q_kernel(float* __restrict__ lg)
{
    const int row = blockIdx.x * 8 + (threadIdx.x >> 5);
    const int lane = threadIdx.x & 31;
    float* p = lg + (size_t)row * 256;
    float4 v0 = *(float4*)&p[lane * 8];
    float4 v1 = *(float4*)&p[lane * 8 + 4];
    float v[8] = { v0.x, v0.y, v0.z, v0.w, v1.x, v1.y, v1.z, v1.w };
    float m = v[0];
#pragma unroll
    for (int i = 1; i < 8; i++) m = fmaxf(m, v[i]);
#pragma unroll
    for (int o = 16; o > 0; o >>= 1) m = fmaxf(m, __shfl_xor_sync(0xffffffffu, m, o));
    float s = 0.f;
#pragma unroll
    for (int i = 0; i < 8; i++) { v[i] = __expf(v[i] - m); s += v[i]; }
#pragma unroll
    for (int o = 16; o > 0; o >>= 1) s += __shfl_xor_sync(0xffffffffu, s, o);
    float inv = 1.f / s;
    *(float4*)&p[lane * 8]     = make_float4(v[0]*inv, v[1]*inv, v[2]*inv, v[3]*inv);
    *(float4*)&p[lane * 8 + 4] = make_float4(v[4]*inv, v[5]*inv, v[6]*inv, v[7]*inv);
}

// ===== attn @ V, k-split, atomics into zeroed g_wt =====
__global__ void __launch_bounds__(256) attnv2_kernel(const float* __restrict__ att)
{
    __shared__ float sv[32][32];
    const int b = blockIdx.z >> 3, h = blockIdx.z & 7;
    const int kc = blockIdx.y, qc = blockIdx.x;
    const int dg = threadIdx.x >> 6, qq = threadIdx.x & 63;
    const int q = qc * 64 + qq;
    {
        int row = threadIdx.x >> 3, c4 = (threadIdx.x & 7) << 2;
        *(float4*)&sv[row][c4] =
            *(const float4*)&g_QKV[((b << 8) + kc * 32 + row) * 768 + 512 + h * 32 + c4];
    }
    __syncthreads();
    const float* ap = att + (((size_t)((b << 3) + h)) * 256 + kc * 32) * 256 + q;
    float acc[8] = {};
#pragma unroll
    for (int kk = 0; kk < 32; kk++) {
        float a = ap[(size_t)kk * 256];
        float4 u0 = *(float4*)&sv[kk][dg * 8];
        float4 u1 = *(float4*)&sv[kk][dg * 8 + 4];
        acc[0]+=a*u0.x; acc[1]+=a*u0.y; acc[2]+=a*u0.z; acc[3]+=a*u0.w;
        acc[4]+=a*u1.x; acc[5]+=a*u1.y; acc[6]+=a*u1.z; acc[7]+=a*u1.w;
    }
    float* wp = &g_wt[((b << 8) + q) * 256 + h * 32 + dg * 8];
#pragma unroll
    for (int j = 0; j < 8; j++) atomicAdd(wp + j, acc[j]);
}

// ===== launch =====
extern "C" void kernel_launch(void* const* d_in, const int* in_sizes, int n_in,
                              void* d_out, int out_size)
{
    const float* nodes   = (const float*)d_in[0];
    const float* edges   = (const float*)d_in[1];
    const float* W_qkv   = (const float*)d_in[2];
    const float* b_qkv   = (const float*)d_in[3];
    const float* W_ss    = (const float*)d_in[4];
    const float* b_ss    = (const float*)d_in[5];
    const float* W_nodes = (const float*)d_in[6];
    const float* b_nodes = (const float*)d_in[7];
    const float* W_edges = (const float*)d_in[8];
    const float* b_edges = (const float*)d_in[9];

    float* out_nodes = (float*)d_out;
    float* out_edges = out_nodes + 512 * 256;

    float *qkvp = nullptr, *attp = nullptr, *wtp = nullptr;
    cudaGetSymbolAddress((void**)&qkvp, g_QKV);
    cudaGetSymbolAddress((void**)&attp, g_att);
    cudaGetSymbolAddress((void**)&wtp, g_wt);
    uint4 *wqh = nullptr, *wql = nullptr, *wnh = nullptr, *wnl = nullptr;
    cudaGetSymbolAddress((void**)&wqh, g_WqkvH);
    cudaGetSymbolAddress((void**)&wql, g_WqkvL);
    cudaGetSymbolAddress((void**)&wnh, g_WndH);
    cudaGetSymbolAddress((void**)&wnl, g_WndL);

    const int EDGE_SMEM = (8704 + 832 + 4224) * sizeof(float);   // 55040 B
    cudaFuncSetAttribute(edge_mma_kernel,
                         cudaFuncAttributeMaxDynamicSharedMemorySize, EDGE_SMEM);

    // edge_mma is the 4th launch (ncu capture point)
    prep_all_kernel<<<152, 256>>>(W_qkv, W_nodes, W_ss, W_edges);
    gemm_mma_kernel<<<(512/32)*(768/64), 256>>>(nodes, wqh, wql, b_qkv, qkvp, 768);
    kfrag_kernel<<<64, 256>>>();
    edge_mma_kernel<<<1024, 256, EDGE_SMEM>>>(edges, b_ss, b_edges, out_edges);
    zero_wt_kernel<<<128, 256>>>();
    softmax_q_kernel<<<512, 256>>>(attp);
    attnv2_kernel<<<dim3(4, 8, 16), 256>>>(attp);
    gemm_mma_kernel<<<(512/32)*(256/64), 256>>>(wtp, wnh, wnl, b_nodes, out_nodes, 256);
}

// round 17
// speedup vs baseline: 1.2264x; 1.0829x over previous
#include <cuda_runtime.h>
#include <cuda_fp16.h>
#include <cstdint>

// ---------------------------------------------------------------------------
// R17: edge = R16 with (1) GEMM2 deferred over kt-pairs (Wed frags loaded once
// per pair -> B traffic halved), (2) sE stored fp16 (stride-36, conflict-free)
// halving GEMM1 A-read traffic. Numerics bit-identical to R16.
// ---------------------------------------------------------------------------

__device__ __forceinline__ void mma16816h(float c[4], const uint32_t a[4],
                                          uint32_t b0, uint32_t b1) {
    asm volatile("mma.sync.aligned.m16n8k16.row.col.f32.f16.f16.f32 "
        "{%0,%1,%2,%3},{%4,%5,%6,%7},{%8,%9},{%0,%1,%2,%3};"
        : "+f"(c[0]), "+f"(c[1]), "+f"(c[2]), "+f"(c[3])
        : "r"(a[0]), "r"(a[1]), "r"(a[2]), "r"(a[3]), "r"(b0), "r"(b1));
}
__device__ __forceinline__ uint32_t pack2h(float v0, float v1) {
    __half2 hh = __floats2half2_rn(v0, v1);
    return *(uint32_t*)&hh;
}
__device__ __forceinline__ void split2h(float v0, float v1, uint32_t& h, uint32_t& l) {
    __half2 hh = __floats2half2_rn(v0, v1);
    float h0 = __low2float(hh), h1 = __high2float(hh);
    __half2 ll = __floats2half2_rn(v0 - h0, v1 - h1);
    h = *(uint32_t*)&hh; l = *(uint32_t*)&ll;
}

// ===== scratch =====
__device__ float g_QKV[512 * 768];
__device__ float g_att[2 * 8 * 256 * 256];  // [b][h][k][q]
__device__ float g_wt[512 * 256];
__device__ uint4 g_Wss[4096];     // [ks4][tp32][lane32] fp16
__device__ uint4 g_Wed[2048];     // [ks16][tp4][lane32] fp16
__device__ uint4 g_WqkvH[24576];  // hi
__device__ uint4 g_WqkvL[24576];  // lo
__device__ uint4 g_WndH[8192];
__device__ uint4 g_WndL[8192];
__device__ uint4 g_Kf[16384];     // frag-ordered K fp16: [b][kt][warp][lane][4]

__global__ void __launch_bounds__(256) zero_wt_kernel()
{
    int i = blockIdx.x * 256 + threadIdx.x;
    ((float4*)g_wt)[i] = make_float4(0.f, 0.f, 0.f, 0.f);
}

__device__ __forceinline__ void fill_img2(const float* __restrict__ W,
                                          uint4* imgH, uint4* imgL,
                                          int idx, int N, int NTP) {
    int lane = idx & 31, tp = (idx >> 5) % NTP, ks = idx / (NTP * 32);
    int gq = lane >> 2, tq = lane & 3;
    uint32_t rh[4], rl[4];
#pragma unroll
    for (int r = 0; r < 4; r++) {
        int tile = 2 * tp + (r >> 1);
        int bsel = r & 1;
        int n = tile * 8 + gq;
        int e0 = ks * 16 + 2 * tq + 8 * bsel;
        split2h(W[e0 * N + n], W[(e0 + 1) * N + n], rh[r], rl[r]);
    }
    imgH[idx] = make_uint4(rh[0], rh[1], rh[2], rh[3]);
    imgL[idx] = make_uint4(rl[0], rl[1], rl[2], rl[3]);
}

// ===== merged prep: 152 blocks =====
__global__ void __launch_bounds__(256) prep_all_kernel(
    const float* __restrict__ W_qkv, const float* __restrict__ W_nodes,
    const float* __restrict__ W_ss, const float* __restrict__ W_edges)
{
    int bidx = blockIdx.x;
    if (bidx < 96) {
        fill_img2(W_qkv, g_WqkvH, g_WqkvL, bidx * 256 + threadIdx.x, 768, 48);
    } else if (bidx < 128) {
        fill_img2(W_nodes, g_WndH, g_WndL, (bidx - 96) * 256 + threadIdx.x, 256, 16);
    } else if (bidx < 144) {
        int idx = (bidx - 128) * 256 + threadIdx.x;
        int lane = idx & 31, tp = (idx >> 5) & 31, ks = idx >> 10;
        int gq = lane >> 2, tq = lane & 3;
        uint32_t r4[4];
#pragma unroll
        for (int r = 0; r < 4; r++) {
            int tile = 2 * tp + (r >> 1);
            int bsel = r & 1;
            int n = tile * 8 + gq;
            int e0 = ks * 16 + 2 * tq + 8 * bsel;
            r4[r] = pack2h(W_ss[e0 * 512 + n], W_ss[(e0 + 1) * 512 + n]);
        }
        g_Wss[idx] = make_uint4(r4[0], r4[1], r4[2], r4[3]);
    } else {
        int idx = (bidx - 144) * 256 + threadIdx.x;
        int lane = idx & 31, tp = (idx >> 5) & 3, ks = idx >> 7;
        int gq = lane >> 2, tq = lane & 3;
        uint32_t r4[4];
#pragma unroll
        for (int r = 0; r < 4; r++) {
            int tile = 2 * tp + (r >> 1);
            int bsel = r & 1;
            int e = tile * 8 + gq;
            int c0 = ks * 16 + 2 * tq + 8 * bsel;
            r4[r] = pack2h(W_edges[c0 * 64 + e], W_edges[(c0 + 1) * 64 + e]);
        }
        g_Wed[idx] = make_uint4(r4[0], r4[1], r4[2], r4[3]);
    }
}

// ===== kfrag: K (qkv cols 256..511) -> frag-ordered fp16 image =====
__global__ void __launch_bounds__(256) kfrag_kernel()
{
    int idx = blockIdx.x * 256 + threadIdx.x;     // 0..16383
    int j = idx & 3, lane = (idx >> 2) & 31, w = (idx >> 7) & 7;
    int kt = (idx >> 10) & 7, b = idx >> 13;
    int wm = w >> 2, wn = w & 3;
    int g = lane >> 2, t = lane & 3;
    int r = wm * 16 + g + ((j >> 1) ? 8 : 0);
    int ltb = (j & 1) * 4;
    const float* p = g_QKV + (size_t)(b*256 + kt*32 + r) * 768 + 256 + wn*64 + 2*t;
    uint32_t o[4];
#pragma unroll
    for (int i = 0; i < 4; i++) {
        float2 v = *(const float2*)(p + (ltb + i) * 8);
        o[i] = pack2h(v.x, v.y);
    }
    g_Kf[idx] = make_uint4(o[0], o[1], o[2], o[3]);
}

// ===== mma GEMM with bias, fp16 3-pass =====
__global__ void __launch_bounds__(256) gemm_mma_kernel(
    const float* __restrict__ A, const uint4* __restrict__ imgH,
    const uint4* __restrict__ imgL,
    const float* __restrict__ bias, float* __restrict__ C, int N)
{
    __shared__ uint32_t sAh[32 * 132];
    __shared__ uint32_t sAl[32 * 132];
    __shared__ float sBias[64];
    const int K = 256;
    const int nb = N >> 6;
    const int m0 = (blockIdx.x / nb) << 5, n0 = (blockIdx.x % nb) << 6;
    const int tid = threadIdx.x;
    const int warp = tid >> 5, lane = tid & 31;
    const int wm = warp >> 2, wn = warp & 3;
    const int g = lane >> 2, t = lane & 3;
    const int NTP = N >> 4;

#pragma unroll
    for (int i = 0; i < 8; i++) {
        int idx4 = tid + i * 256;
        int row = idx4 >> 6, c4 = idx4 & 63;
        float4 v = *(const float4*)&A[(m0 + row) * K + c4 * 4];
        uint32_t h0, l0, h1, l1;
        split2h(v.x, v.y, h0, l0);
        split2h(v.z, v.w, h1, l1);
        *(uint2*)&sAh[row * 132 + c4 * 2] = make_uint2(h0, h1);
        *(uint2*)&sAl[row * 132 + c4 * 2] = make_uint2(l0, l1);
    }
    if (tid < 64) sBias[tid] = bias[n0 + tid];
    __syncthreads();

    const int r0 = wm * 16 + g, r1 = r0 + 8;
    float acc0[4] = {}, acc1[4] = {};
#pragma unroll
    for (int ks = 0; ks < 16; ks++) {
        uint32_t ah[4], al[4];
        ah[0] = sAh[r0 * 132 + ks * 8 + t];     al[0] = sAl[r0 * 132 + ks * 8 + t];
        ah[1] = sAh[r1 * 132 + ks * 8 + t];     al[1] = sAl[r1 * 132 + ks * 8 + t];
        ah[2] = sAh[r0 * 132 + ks * 8 + 4 + t]; al[2] = sAl[r0 * 132 + ks * 8 + 4 + t];
        ah[3] = sAh[r1 * 132 + ks * 8 + 4 + t]; al[3] = sAl[r1 * 132 + ks * 8 + 4 + t];
        int bi = ((ks * NTP) + (n0 >> 4) + wn) * 32 + lane;
        uint4 bh = imgH[bi];
        uint4 bl = imgL[bi];
        mma16816h(acc0, ah, bh.x, bh.y); mma16816h(acc1, ah, bh.z, bh.w);
        mma16816h(acc0, al, bh.x, bh.y); mma16816h(acc1, al, bh.z, bh.w);
        mma16816h(acc0, ah, bl.x, bl.y); mma16816h(acc1, ah, bl.z, bl.w);
    }
    const int cl = wn * 16 + 2 * t;
    const int c0 = n0 + cl;
    *(float2*)&C[(m0 + r0) * N + c0]     = make_float2(acc0[0] + sBias[cl],   acc0[1] + sBias[cl+1]);
    *(float2*)&C[(m0 + r1) * N + c0]     = make_float2(acc0[2] + sBias[cl],   acc0[3] + sBias[cl+1]);
    *(float2*)&C[(m0 + r0) * N + c0 + 8] = make_float2(acc1[0] + sBias[cl+8], acc1[1] + sBias[cl+9]);
    *(float2*)&C[(m0 + r1) * N + c0 + 8] = make_float2(acc1[2] + sBias[cl+8], acc1[3] + sBias[cl+9]);
}

// ===== main edge kernel: fp16 1-pass; sE fp16; GEMM2 deferred per kt-pair ===
__global__ void __launch_bounds__(256, 2) edge_mma_kernel(
    const float* __restrict__ edges, const float* __restrict__ b_ss,
    const float* __restrict__ b_edges, float* __restrict__ out_edges)
{
    extern __shared__ float sm[];
    uint32_t* sE16 = (uint32_t*)sm;            // [4][32][36] fp16x2 = 4608 w
    float* sQ   = sm + 4608;                   // 256
    float* sBsh = sm + 4864;                   // 256
    float* sBsc = sm + 5120;                   // 256
    float* sBed = sm + 5376;                   // 64
    uint32_t* sA2 = (uint32_t*)(sm + 5440);    // [2][32][132] = 8448 w

    const int tid = threadIdx.x;
    const int warp = tid >> 5, lane = tid & 31;
    const int wm = warp >> 2, wn = warp & 3;
    const int g = lane >> 2, t = lane & 3;
    const int b = blockIdx.x >> 9;
    const int q = (blockIdx.x >> 1) & 255;
    const int half = blockIdx.x & 1;
    const int r0 = wm * 16 + g, r1 = r0 + 8;

    const float* ep = edges + (((size_t)(b * 256 + q)) * 256 + half * 128) * 64;

    if (tid < 64)       *(float4*)&sQ[tid*4]   = *(const float4*)&g_QKV[(b*256+q)*768 + tid*4];
    else if (tid < 128) *(float4*)&sBsh[(tid-64)*4]  = *(const float4*)&b_ss[(tid-64)*4];
    else if (tid < 192) *(float4*)&sBsc[(tid-128)*4] = *(const float4*)&b_ss[256+(tid-128)*4];
    else if (tid < 208) *(float4*)&sBed[(tid-192)*4] = *(const float4*)&b_edges[(tid-192)*4];

    // stage all 4 edge tiles as fp16 (row stride 36 words: banks 4g+t distinct)
    {
        const int er = tid >> 4, ec = (tid & 15) << 2;
#pragma unroll
        for (int i = 0; i < 8; i++) {
            int tile = i >> 1;
            int row = er + (i & 1) * 16;
            float4 v = *(const float4*)(ep + (size_t)(tile*32 + row) * 64 + ec);
            *(uint2*)&sE16[tile*1152 + row*36 + (ec >> 1)] =
                make_uint2(pack2h(v.x, v.y), pack2h(v.z, v.w));
        }
    }
    __syncthreads();

    for (int kp = 0; kp < 2; kp++) {
#pragma unroll
        for (int kk2 = 0; kk2 < 2; kk2++) {
            const int kt4 = kp * 2 + kk2;
            const int kt = half * 4 + kt4;
            const uint32_t* sEc = sE16 + kt4 * 1152;

            // ---- GEMM1: shift(acc 0..7) + scale(acc 8..15), fp16 1-pass ----
            float acc[16][4];
#pragma unroll
            for (int i = 0; i < 16; i++) { acc[i][0]=acc[i][1]=acc[i][2]=acc[i][3]=0.f; }
#pragma unroll
            for (int ks = 0; ks < 4; ks++) {
                uint32_t Ah[4];
                {
                    int w0 = ks * 8 + t;
                    Ah[0] = sEc[r0*36 + w0];
                    Ah[1] = sEc[r1*36 + w0];
                    Ah[2] = sEc[r0*36 + w0 + 4];
                    Ah[3] = sEc[r1*36 + w0 + 4];
                }
#pragma unroll
                for (int tpi = 0; tpi < 4; tpi++) {
                    uint4 bh = g_Wss[(ks*32 + 4*wn + tpi)*32 + lane];
                    mma16816h(acc[2*tpi],   Ah, bh.x, bh.y);
                    mma16816h(acc[2*tpi+1], Ah, bh.z, bh.w);
                    uint4 ch = g_Wss[(ks*32 + 16 + 4*wn + tpi)*32 + lane];
                    mma16816h(acc[8+2*tpi],   Ah, ch.x, ch.y);
                    mma16816h(acc[8+2*tpi+1], Ah, ch.z, ch.w);
                }
            }

            // ---- K frags: 4 coalesced LDG.128 ----
            uint32_t kr[16];
            {
                uint4* k4 = (uint4*)kr;
                size_t kb = ((((size_t)b*8 + kt)*8 + warp)*32 + lane)*4;
                k4[0] = g_Kf[kb];     k4[1] = g_Kf[kb + 1];
                k4[2] = g_Kf[kb + 2]; k4[3] = g_Kf[kb + 3];
            }

            // ---- epilogue: ne, logits, lrelu -> sA2[kk2] ----
            uint32_t* a2w = sA2 + kk2 * 4224;
            float lg00 = 0.f, lg01 = 0.f, lg10 = 0.f, lg11 = 0.f;
#pragma unroll
            for (int lt = 0; lt < 8; lt++) {
                int c0 = wn * 64 + lt * 8 + 2 * t;
                float2 k0v = __half22float2(*(__half2*)&kr[lt]);
                float2 k1v = __half22float2(*(__half2*)&kr[8 + lt]);
                float q0 = sQ[c0], q1 = sQ[c0+1];
                float qk00 = q0 * k0v.x, qk01 = q1 * k0v.y;
                float qk10 = q0 * k1v.x, qk11 = q1 * k1v.y;
                float ne00 = fmaf(qk00, acc[8+lt][0] + sBsc[c0],   qk00) + acc[lt][0] + sBsh[c0];
                float ne01 = fmaf(qk01, acc[8+lt][1] + sBsc[c0+1], qk01) + acc[lt][1] + sBsh[c0+1];
                float ne10 = fmaf(qk10, acc[8+lt][2] + sBsc[c0],   qk10) + acc[lt][2] + sBsh[c0];
                float ne11 = fmaf(qk11, acc[8+lt][3] + sBsc[c0+1], qk11) + acc[lt][3] + sBsh[c0+1];
                if (lt < 4) { lg00 += ne00 + ne01; lg10 += ne10 + ne11; }
                else        { lg01 += ne00 + ne01; lg11 += ne10 + ne11; }
                float p00 = ne00 > 0.f ? ne00 : 0.1f*ne00;
                float p01 = ne01 > 0.f ? ne01 : 0.1f*ne01;
                float p10 = ne10 > 0.f ? ne10 : 0.1f*ne10;
                float p11 = ne11 > 0.f ? ne11 : 0.1f*ne11;
                int cp = wn * 32 + lt * 4 + t;
                a2w[r0*132 + cp] = pack2h(p00, p01);
                a2w[r1*132 + cp] = pack2h(p10, p11);
            }
            lg00 += __shfl_xor_sync(0xffffffffu, lg00, 1); lg00 += __shfl_xor_sync(0xffffffffu, lg00, 2);
            lg01 += __shfl_xor_sync(0xffffffffu, lg01, 1); lg01 += __shfl_xor_sync(0xffffffffu, lg01, 2);
            lg10 += __shfl_xor_sync(0xffffffffu, lg10, 1); lg10 += __shfl_xor_sync(0xffffffffu, lg10, 2);
            lg11 += __shfl_xor_sync(0xffffffffu, lg11, 1); lg11 += __shfl_xor_sync(0xffffffffu, lg11, 2);
            if (t == 0) {
                const float SC = 0.17677669529663687f;
                int kk = kt * 32;
                g_att[(((size_t)(b*8 + 2*wn+0))*256 + kk + r0)*256 + q] = lg00 * SC;
                g_att[(((size_t)(b*8 + 2*wn+1))*256 + kk + r0)*256 + q] = lg01 * SC;
                g_att[(((size_t)(b*8 + 2*wn+0))*256 + kk + r1)*256 + q] = lg10 * SC;
                g_att[(((size_t)(b*8 + 2*wn+1))*256 + kk + r1)*256 + q] = lg11 * SC;
            }
        }
        __syncthreads();   // both sA2 buffers complete

        // ---- GEMM2 for the kt-pair: Wed frags loaded ONCE ----
        float c2[2][2][4];
#pragma unroll
        for (int i = 0; i < 2; i++)
#pragma unroll
            for (int j = 0; j < 2; j++)
                { c2[i][j][0]=c2[i][j][1]=c2[i][j][2]=c2[i][j][3]=0.f; }
#pragma unroll
        for (int ks = 0; ks < 16; ks++) {
            uint4 bh = g_Wed[(ks*4 + wn)*32 + lane];
#pragma unroll
            for (int kt2 = 0; kt2 < 2; kt2++) {
                const uint32_t* a2 = sA2 + kt2 * 4224;
                uint32_t ah[4];
                ah[0] = a2[r0*132 + ks*8 + t];
                ah[1] = a2[r1*132 + ks*8 + t];
                ah[2] = a2[r0*132 + ks*8 + 4 + t];
                ah[3] = a2[r1*132 + ks*8 + 4 + t];
                mma16816h(c2[kt2][0], ah, bh.x, bh.y);
                mma16816h(c2[kt2][1], ah, bh.z, bh.w);
            }
        }
#pragma unroll
        for (int kt2 = 0; kt2 < 2; kt2++) {
            const int kt = half * 4 + kp * 2 + kt2;
            float* op = out_edges + (((size_t)(b*256+q))*256 + kt*32)*64;
            int e0 = wn * 16 + 2 * t;
            *(float2*)&op[r0*64 + e0]     = make_float2(c2[kt2][0][0] + sBed[e0],   c2[kt2][0][1] + sBed[e0+1]);
            *(float2*)&op[r1*64 + e0]     = make_float2(c2[kt2][0][2] + sBed[e0],   c2[kt2][0][3] + sBed[e0+1]);
            *(float2*)&op[r0*64 + e0 + 8] = make_float2(c2[kt2][1][0] + sBed[e0+8], c2[kt2][1][1] + sBed[e0+9]);
            *(float2*)&op[r1*64 + e0 + 8] = make_float2(c2[kt2][1][2] + sBed[e0+8], c2[kt2][1][3] + sBed[e0+9]);
        }
        __syncthreads();   // sA2 free for next pair
    }
}

// ===== softmax over q for each (b,h,k) =====
__global__ void __launch_bounds__(256) softmax_q_kernel(float* __restrict__ lg)
{
    const int row = blockIdx.x * 8 + (threadIdx.x >> 5);
    const int lane = threadIdx.x & 31;
    float* p = lg + (size_t)row * 256;
    float4 v0 = *(float4*)&p[lane * 8];
    float4 v1 = *(float4*)&p[lane * 8 + 4];
    float v[8] = { v0.x, v0.y, v0.z, v0.w, v1.x, v1.y, v1.z, v1.w };
    float m = v[0];
#pragma unroll
    for (int i = 1; i < 8; i++) m = fmaxf(m, v[i]);
#pragma unroll
    for (int o = 16; o > 0; o >>= 1) m = fmaxf(m, __shfl_xor_sync(0xffffffffu, m, o));
    float s = 0.f;
#pragma unroll
    for (int i = 0; i < 8; i++) { v[i] = __expf(v[i] - m); s += v[i]; }
#pragma unroll
    for (int o = 16; o > 0; o >>= 1) s += __shfl_xor_sync(0xffffffffu, s, o);
    float inv = 1.f / s;
    *(float4*)&p[lane * 8]     = make_float4(v[0]*inv, v[1]*inv, v[2]*inv, v[3]*inv);
    *(float4*)&p[lane * 8 + 4] = make_float4(v[4]*inv, v[5]*inv, v[6]*inv, v[7]*inv);
}

// ===== attn @ V, k-split, atomics into zeroed g_wt =====
__global__ void __launch_bounds__(256) attnv2_kernel(const float* __restrict__ att)
{
    __shared__ float sv[32][32];
    const int b = blockIdx.z >> 3, h = blockIdx.z & 7;
    const int kc = blockIdx.y, qc = blockIdx.x;
    const int dg = threadIdx.x >> 6, qq = threadIdx.x & 63;
    const int q = qc * 64 + qq;
    {
        int row = threadIdx.x >> 3, c4 = (threadIdx.x & 7) << 2;
        *(float4*)&sv[row][c4] =
            *(const float4*)&g_QKV[((b << 8) + kc * 32 + row) * 768 + 512 + h * 32 + c4];
    }
    __syncthreads();
    const float* ap = att + (((size_t)((b << 3) + h)) * 256 + kc * 32) * 256 + q;
    float acc[8] = {};
#pragma unroll
    for (int kk = 0; kk < 32; kk++) {
        float a = ap[(size_t)kk * 256];
        float4 u0 = *(float4*)&sv[kk][dg * 8];
        float4 u1 = *(float4*)&sv[kk][dg * 8 + 4];
        acc[0]+=a*u0.x; acc[1]+=a*u0.y; acc[2]+=a*u0.z; acc[3]+=a*u0.w;
        acc[4]+=a*u1.x; acc[5]+=a*u1.y; acc[6]+=a*u1.z; acc[7]+=a*u1.w;
    }
    float* wp = &g_wt[((b << 8) + q) * 256 + h * 32 + dg * 8];
#pragma unroll
    for (int j = 0; j < 8; j++) atomicAdd(wp + j, acc[j]);
}

// ===== launch =====
extern "C" void kernel_launch(void* const* d_in, const int* in_sizes, int n_in,
                              void* d_out, int out_size)
{
    const float* nodes   = (const float*)d_in[0];
    const float* edges   = (const float*)d_in[1];
    const float* W_qkv   = (const float*)d_in[2];
    const float* b_qkv   = (const float*)d_in[3];
    const float* W_ss    = (const float*)d_in[4];
    const float* b_ss    = (const float*)d_in[5];
    const float* W_nodes = (const float*)d_in[6];
    const float* b_nodes = (const float*)d_in[7];
    const float* W_edges = (const float*)d_in[8];
    const float* b_edges = (const float*)d_in[9];

    float* out_nodes = (float*)d_out;
    float* out_edges = out_nodes + 512 * 256;

    float *qkvp = nullptr, *attp = nullptr, *wtp = nullptr;
    cudaGetSymbolAddress((void**)&qkvp, g_QKV);
    cudaGetSymbolAddress((void**)&attp, g_att);
    cudaGetSymbolAddress((void**)&wtp, g_wt);
    uint4 *wqh = nullptr, *wql = nullptr, *wnh = nullptr, *wnl = nullptr;
    cudaGetSymbolAddress((void**)&wqh, g_WqkvH);
    cudaGetSymbolAddress((void**)&wql, g_WqkvL);
    cudaGetSymbolAddress((void**)&wnh, g_WndH);
    cudaGetSymbolAddress((void**)&wnl, g_WndL);

    // sE16 4608 + sQ/biases 832 + sA2 8448 = 13888 words = 55552 B
    const int EDGE_SMEM = 13888 * sizeof(float);
    cudaFuncSetAttribute(edge_mma_kernel,
                         cudaFuncAttributeMaxDynamicSharedMemorySize, EDGE_SMEM);

    // edge_mma is the 4th launch (ncu capture point)
    prep_all_kernel<<<152, 256>>>(W_qkv, W_nodes, W_ss, W_edges);
    gemm_mma_kernel<<<(512/32)*(768/64), 256>>>(nodes, wqh, wql, b_qkv, qkvp, 768);
    kfrag_kernel<<<64, 256>>>();
    edge_mma_kernel<<<1024, 256, EDGE_SMEM>>>(edges, b_ss, b_edges, out_edges);
    zero_wt_kernel<<<128, 256>>>();
    softmax_q_kernel<<<512, 256>>>(attp);
    attnv2_kernel<<<dim3(4, 8, 16), 256>>>(attp);
    gemm_mma_kernel<<<(512/32)*(256/64), 256>>>(wtp, wnh, wnl, b_nodes, out_nodes, 256);
}